// round 5
// baseline (speedup 1.0000x reference)
#include <cuda_runtime.h>

#define T_DIM 1024
#define O_DIM 512
#define D_DIM 256
#define H_DIM 512
#define M_DIM (T_DIM + O_DIM)   // 1536

// Scratch (no allocations allowed)
__device__ float g_A[M_DIM * H_DIM];   // rows 0..1023: ht ; rows 1024..1535: ho + b1
__device__ float g_u[M_DIM];           // g_A[m] . W2

typedef unsigned long long u64;

__device__ __forceinline__ u64 addx2(u64 a, u64 b) {
    u64 r; asm("add.rn.f32x2 %0,%1,%2;" : "=l"(r) : "l"(a), "l"(b)); return r;
}
__device__ __forceinline__ u64 fmax2(u64 a, u64 b, u64 c) {
    u64 r; asm("fma.rn.f32x2 %0,%1,%2,%3;" : "=l"(r) : "l"(a), "l"(b), "l"(c)); return r;
}

union F2U { float2 f; u64 u; };

// ---------------------------------------------------------------------------
// Kernel 1: combined SGEMM.
//   m < 1024:  g_A[m][h] = sum_k z_t[m][k]   * W1[k][h]
//   m >= 1024: g_A[m][h] = sum_k z_o[m-T][k] * W1[256+k][h] + b1[h]
// Tiles: BM=64, BN=64, BK=16. 256 threads, 4x4 per thread.
// ---------------------------------------------------------------------------
__global__ __launch_bounds__(256) void gemm_kernel(
    const float* __restrict__ z_t, const float* __restrict__ z_o,
    const float* __restrict__ W1,  const float* __restrict__ b1)
{
    __shared__ __align__(16) float Zs[16][64];
    __shared__ __align__(16) float Ws[16][64];

    const int tid = threadIdx.x;
    const int tx = tid & 15, ty = tid >> 4;
    const int m0 = blockIdx.y * 64;
    const int h0 = blockIdx.x * 64;
    const bool is_o = (m0 >= T_DIM);
    const float* Z = is_o ? z_o : z_t;
    const int mrow0 = is_o ? (m0 - T_DIM) : m0;
    const int kbase = is_o ? D_DIM : 0;

    // staging mapping
    const int zm = tid >> 2;        // 0..63  (m within tile)
    const int zk = (tid & 3) * 4;   // 0,4,8,12
    const int wk = tid >> 4;        // 0..15  (k within chunk)
    const int wh = (tid & 15) * 4;  // 0..60

    const float* zrowp = Z + (mrow0 + zm) * D_DIM;

    float acc[4][4] = {};

    // prefetch chunk 0
    float4 zr = *(const float4*)(zrowp + zk);
    float4 wr = *(const float4*)(W1 + (kbase + wk) * H_DIM + h0 + wh);

    for (int c = 0; c < 16; ++c) {
        Zs[zk + 0][zm] = zr.x; Zs[zk + 1][zm] = zr.y;
        Zs[zk + 2][zm] = zr.z; Zs[zk + 3][zm] = zr.w;
        *(float4*)&Ws[wk][wh] = wr;
        __syncthreads();
        if (c < 15) {
            const int k0 = (c + 1) * 16;
            zr = *(const float4*)(zrowp + k0 + zk);
            wr = *(const float4*)(W1 + (kbase + k0 + wk) * H_DIM + h0 + wh);
        }
        #pragma unroll
        for (int k = 0; k < 16; ++k) {
            float4 a = *(const float4*)&Zs[k][ty * 4];
            float4 b = *(const float4*)&Ws[k][tx * 4];
            float av[4] = {a.x, a.y, a.z, a.w};
            float bv[4] = {b.x, b.y, b.z, b.w};
            #pragma unroll
            for (int i = 0; i < 4; ++i)
                #pragma unroll
                for (int j = 0; j < 4; ++j)
                    acc[i][j] = fmaf(av[i], bv[j], acc[i][j]);
        }
        __syncthreads();
    }

    float bj[4] = {0.f, 0.f, 0.f, 0.f};
    if (is_o) {
        #pragma unroll
        for (int j = 0; j < 4; ++j) bj[j] = b1[h0 + tx * 4 + j];
    }
    #pragma unroll
    for (int i = 0; i < 4; ++i) {
        float4 v = make_float4(acc[i][0] + bj[0], acc[i][1] + bj[1],
                               acc[i][2] + bj[2], acc[i][3] + bj[3]);
        *(float4*)&g_A[(m0 + ty * 4 + i) * H_DIM + h0 + tx * 4] = v;
    }
}

// ---------------------------------------------------------------------------
// Kernel 2: g_u[m] = g_A[m] . W2   (one warp per row)
// ---------------------------------------------------------------------------
__global__ __launch_bounds__(256) void rowdot_kernel(const float* __restrict__ W2)
{
    const int warp = blockIdx.x * 8 + (threadIdx.x >> 5);
    const int lane = threadIdx.x & 31;
    const float* row = g_A + warp * H_DIM;
    float s = 0.f;
    #pragma unroll
    for (int q = 0; q < 4; ++q) {
        const int idx = q * 128 + lane * 4;
        float4 a = *(const float4*)(row + idx);
        float4 w = *(const float4*)(W2 + idx);
        s += a.x * w.x + a.y * w.y + a.z * w.z + a.w * w.w;
    }
    #pragma unroll
    for (int d = 16; d >= 1; d >>= 1) s += __shfl_xor_sync(0xFFFFFFFFu, s, d);
    if (lane == 0) g_u[warp] = s;
}

// ---------------------------------------------------------------------------
// Kernel 3: main abs-bilinear loop.
// out[t][o] = 0.505*(u[t]+u[T+o]) + 0.495 * sum_h |A[t][h]+A[T+o][h]| * w[h] + b2
// Tile 64(t) x 64(o), 256 threads (16x16), 4x4 per thread, h vectorized by 2
// (f32x2). h-chunks of 32 pairs staged transposed in shared.
// ---------------------------------------------------------------------------
__global__ __launch_bounds__(256) void cfm_main_kernel(
    const float* __restrict__ W2, const float* __restrict__ b2,
    float* __restrict__ out)
{
    __shared__ __align__(16) u64 As[32][64];   // [h-pair][t]
    __shared__ __align__(16) u64 Bs[32][64];   // [h-pair][o]
    __shared__ u64 wsm[32];

    const int tid = threadIdx.x;
    const int tx = tid & 15, ty = tid >> 4;
    const int t0 = blockIdx.y * 64;
    const int o0 = blockIdx.x * 64;

    // staging mapping: each thread loads 16 consecutive floats (8 h-pairs) of one row
    const int srow = tid >> 2;           // 0..63
    const int pg   = (tid & 3) * 8;      // pair-group start: 0,8,16,24
    const float* Arow = g_A + (t0 + srow) * H_DIM + pg * 2;
    const float* Brow = g_A + (T_DIM + o0 + srow) * H_DIM + pg * 2;

    u64 acc[4][4] = {};

    float4 ra[4], rb[4];
    #pragma unroll
    for (int r = 0; r < 4; ++r) {
        ra[r] = *(const float4*)(Arow + r * 4);
        rb[r] = *(const float4*)(Brow + r * 4);
    }
    float2 wf = make_float2(0.f, 0.f);
    if (tid < 32) wf = *(const float2*)(W2 + tid * 2);

    const u64 ABSM = 0x7FFFFFFF7FFFFFFFULL;

    for (int c = 0; c < 8; ++c) {
        #pragma unroll
        for (int r = 0; r < 4; ++r) {
            F2U p0, p1, q0, q1;
            p0.f = make_float2(ra[r].x, ra[r].y);
            p1.f = make_float2(ra[r].z, ra[r].w);
            q0.f = make_float2(rb[r].x, rb[r].y);
            q1.f = make_float2(rb[r].z, rb[r].w);
            As[pg + r * 2 + 0][srow] = p0.u;
            As[pg + r * 2 + 1][srow] = p1.u;
            Bs[pg + r * 2 + 0][srow] = q0.u;
            Bs[pg + r * 2 + 1][srow] = q1.u;
        }
        if (tid < 32) { F2U pw; pw.f = wf; wsm[tid] = pw.u; }
        __syncthreads();
        if (c < 7) {
            const int off = (c + 1) * 64;   // 64 floats = 32 pairs per chunk
            #pragma unroll
            for (int r = 0; r < 4; ++r) {
                ra[r] = *(const float4*)(Arow + off + r * 4);
                rb[r] = *(const float4*)(Brow + off + r * 4);
            }
            if (tid < 32) wf = *(const float2*)(W2 + (c + 1) * 64 + tid * 2);
        }
        #pragma unroll 8
        for (int k = 0; k < 32; ++k) {
            u64 a2[4], b2v[4];
            ulonglong2 pa0 = *(const ulonglong2*)&As[k][ty * 4];
            ulonglong2 pa1 = *(const ulonglong2*)&As[k][ty * 4 + 2];
            ulonglong2 pb0 = *(const ulonglong2*)&Bs[k][tx * 4];
            ulonglong2 pb1 = *(const ulonglong2*)&Bs[k][tx * 4 + 2];
            a2[0] = pa0.x; a2[1] = pa0.y; a2[2] = pa1.x; a2[3] = pa1.y;
            b2v[0] = pb0.x; b2v[1] = pb0.y; b2v[2] = pb1.x; b2v[3] = pb1.y;
            const u64 w2 = wsm[k];
            #pragma unroll
            for (int i = 0; i < 4; ++i)
                #pragma unroll
                for (int j = 0; j < 4; ++j) {
                    u64 s = addx2(a2[i], b2v[j]);
                    s &= ABSM;                       // |.| on both lanes (LOP3 x2, alu pipe)
                    acc[i][j] = fmax2(s, w2, acc[i][j]);
                }
        }
        __syncthreads();
    }

    // epilogue
    const float b2v = b2[0];
    float ut[4], uo[4];
    #pragma unroll
    for (int i = 0; i < 4; ++i) ut[i] = g_u[t0 + ty * 4 + i];
    #pragma unroll
    for (int j = 0; j < 4; ++j) uo[j] = g_u[T_DIM + o0 + tx * 4 + j];

    #pragma unroll
    for (int i = 0; i < 4; ++i) {
        float v[4];
        #pragma unroll
        for (int j = 0; j < 4; ++j) {
            F2U cu; cu.u = acc[i][j];
            const float S = cu.f.x + cu.f.y;
            v[j] = 0.505f * (ut[i] + uo[j]) + 0.495f * S + b2v;
        }
        *(float4*)&out[(t0 + ty * 4 + i) * O_DIM + o0 + tx * 4] =
            make_float4(v[0], v[1], v[2], v[3]);
    }
}

// ---------------------------------------------------------------------------
extern "C" void kernel_launch(void* const* d_in, const int* in_sizes, int n_in,
                              void* d_out, int out_size)
{
    const float* z_t = (const float*)d_in[0];   // [1024,256]
    const float* z_o = (const float*)d_in[1];   // [512,256]
    const float* W1  = (const float*)d_in[2];   // [512,512]
    const float* b1  = (const float*)d_in[3];   // [512]
    const float* W2  = (const float*)d_in[4];   // [512,1]
    const float* b2  = (const float*)d_in[5];   // [1]
    float* out = (float*)d_out;                 // [1024,512]

    (void)in_sizes; (void)n_in; (void)out_size;

    gemm_kernel<<<dim3(H_DIM / 64, M_DIM / 64), 256>>>(z_t, z_o, W1, b1);
    rowdot_kernel<<<M_DIM / 8, 256>>>(W2);
    cfm_main_kernel<<<dim3(O_DIM / 64, T_DIM / 64), 256>>>(W2, b2, out);
}